// round 11
// baseline (speedup 1.0000x reference)
#include <cuda_runtime.h>
#include <math.h>
#include <stdint.h>

// GNN on complete per-scene digraphs: B=64 scenes, N=128 nodes.
// segment_mean at node d = (scene_sum(h) - h[d]) / 127.
// R11 = R10 (best, 18.6us) with the separate colsum pass deleted:
//  - colsum fused into emit (scalar warp butterfly + lane0 static atomics,
//    the R6-proven variant), distinct cs slots per layer, pre-zeroed
//  - per layer: 3 __syncthreads + 1 cluster barrier (was 5+1)
//  - float4 srow loads (STRIDE=84), packed fma.rn.f32x2 node terms
//  - float4 weight prologue loads
// 2-CTA cluster/scene, 512 thr/CTA (8 thr/node, JT 8/8/4/2), pull-style bp
// exchange with ping-pong slots, base = bias + bp_local + bp_peer.

#define NODES    128
#define LOCALN   64
#define SCENES   64
#define THREADS  512
#define STRIDE   84
#define INV127   (1.0f/127.0f)

typedef unsigned long long u64;

// smem layout (float indices)
#define S_W1s    0            // 5*64  (W1/127)
#define S_W1s128 320          // 5*64  (W1*128/127)
#define S_B1     640          // 64
#define S_W2s    704          // 75*64
#define S_B2     5504         // 64
#define S_W3s    5568         // 64*32
#define S_B3     7616         // 32
#define S_W4s    7648         // 32*16
#define S_B4     8160         // 16
#define S_WNs    8176         // 16*2
#define S_BN     8208         // 2 (+2)
#define S_WG1    8212         // 16*8
#define S_BG1    8340         // 8
#define S_WG2    8348         // 8
#define S_BG2    8356         // 1 (+3)
#define S_A      8360         // 64*84
#define S_BUF    13736        // 64*84
#define S_CS2    19112        // 80: [0..63] h1 csl (atomics), [64..74] info csl
#define S_CS3    19192        // 64
#define S_CS4    19256        // 32
#define S_CS5    19320        // 16 (64-aligned gap left after CS4)
#define S_BASE   19336        // 64
#define S_BP     19400        // 2 slots x 64
#define S_SCENEB 19528        // 16
#define S_PART   19544        // 176 (info colsum partials)
#define S_TOT    19720
#define SMEM_BYTES (S_TOT * 4)   // 78880 B

__device__ __forceinline__ uint32_t smem_u32(const void* p) {
    uint32_t a;
    asm("{ .reg .u64 t; cvta.to.shared.u64 t, %1; cvt.u32.u64 %0, t; }"
        : "=r"(a) : "l"(p));
    return a;
}
__device__ __forceinline__ float ld_peer_f32(uint32_t la, uint32_t peer) {
    uint32_t ra;
    asm("mapa.shared::cluster.u32 %0, %1, %2;" : "=r"(ra) : "r"(la), "r"(peer));
    float v;
    asm volatile("ld.shared::cluster.f32 %0, [%1];" : "=f"(v) : "r"(ra));
    return v;
}
#define CLUSTER_ARRIVE() asm volatile("barrier.cluster.arrive.aligned;" ::: "memory")
#define CLUSTER_WAIT()   asm volatile("barrier.cluster.wait.aligned;"   ::: "memory")

// ---- packed f32x2 helpers ----
__device__ __forceinline__ u64 pack2(float lo, float hi) {
    u64 r; asm("mov.b64 %0, {%1, %2};" : "=l"(r) : "f"(lo), "f"(hi)); return r;
}
__device__ __forceinline__ void unpack2(u64 v, float& lo, float& hi) {
    asm("mov.b64 {%0, %1}, %2;" : "=f"(lo), "=f"(hi) : "l"(v));
}
__device__ __forceinline__ u64 fma2(u64 a, u64 b, u64 c) {
    u64 r; asm("fma.rn.f32x2 %0, %1, %2, %3;" : "=l"(r) : "l"(a), "l"(b), "l"(c)); return r;
}

// one k-step of the packed node term
template<int OUT, int JT>
__device__ __forceinline__ void nt_step(float a, const float* __restrict__ Ws,
                                        int k, int j0, u64* acc2) {
    u64 aa = pack2(a, a);
    if constexpr (JT == 8) {
        const ulonglong2* wr = reinterpret_cast<const ulonglong2*>(Ws + k * OUT + j0);
        ulonglong2 w0 = wr[0], w1 = wr[1];
        acc2[0] = fma2(aa, w0.x, acc2[0]);
        acc2[1] = fma2(aa, w0.y, acc2[1]);
        acc2[2] = fma2(aa, w1.x, acc2[2]);
        acc2[3] = fma2(aa, w1.y, acc2[3]);
    } else if constexpr (JT == 4) {
        ulonglong2 w = *reinterpret_cast<const ulonglong2*>(Ws + k * OUT + j0);
        acc2[0] = fma2(aa, w.x, acc2[0]);
        acc2[1] = fma2(aa, w.y, acc2[1]);
    } else {
        u64 w = *reinterpret_cast<const u64*>(Ws + k * OUT + j0);
        acc2[0] = fma2(aa, w, acc2[0]);
    }
}

// node term with float4 srow loads: acc2 covers columns j0..j0+JT-1
template<int IN, int OUT, int JT>
__device__ __forceinline__ void nodeterm2(const float* __restrict__ S, int soff,
                                          const float* __restrict__ Ws,
                                          u64* __restrict__ acc2, int n, int j0) {
    #pragma unroll
    for (int v = 0; v < JT / 2; v++) acc2[v] = 0ull;
    const float* srow = S + n * STRIDE + soff;
    constexpr int KB = IN / 4;
    const float4* s4 = reinterpret_cast<const float4*>(srow);
    for (int kb = 0; kb < KB; kb++) {
        float4 a4 = s4[kb];
        nt_step<OUT, JT>(a4.x, Ws, 4 * kb + 0, j0, acc2);
        nt_step<OUT, JT>(a4.y, Ws, 4 * kb + 1, j0, acc2);
        nt_step<OUT, JT>(a4.z, Ws, 4 * kb + 2, j0, acc2);
        nt_step<OUT, JT>(a4.w, Ws, 4 * kb + 3, j0, acc2);
    }
    #pragma unroll
    for (int k = KB * 4; k < IN; k++)
        nt_step<OUT, JT>(srow[k], Ws, k, j0, acc2);
}

// One GCN layer with FUSED colsum:
//   basepart(cs_prev from previous emit) -> ARRIVE -> nodeterm -> WAIT ->
//   combine (pull peer bp) -> sync -> emit+butterfly+atomics(cs_next) -> sync
template<int IN, int OUT, int JT>
__device__ __forceinline__ void layer_run(
    float* __restrict__ sm, const float* __restrict__ Ssrc, int soff,
    float* __restrict__ D,
    const float* __restrict__ cs_prev, float* __restrict__ cs_next,
    const float* __restrict__ Wb, const float* __restrict__ Wn_,
    const float* __restrict__ bias,
    int slot, int tid, int lane, int n, int q, uint32_t peer, uint32_t smbase)
{
    float* base = sm + S_BASE;
    float* bp   = sm + S_BP + slot * 64;

    // base-partial on LOCAL colsum: 4 threads per output column
    if (tid < 4 * OUT) {
        const int j = tid >> 2, p = tid & 3;
        float s = 0.f;
        for (int k = p; k < IN; k += 4) s += cs_prev[k] * Wb[k * OUT + j];
        s += __shfl_xor_sync(0xffffffffu, s, 1);
        s += __shfl_xor_sync(0xffffffffu, s, 2);
        if (p == 0) bp[j] = s;
    }
    CLUSTER_ARRIVE();

    const int j0 = q * JT;
    u64 acc2[JT / 2];
    nodeterm2<IN, OUT, JT>(Ssrc, soff, Wn_, acc2, n, j0);

    CLUSTER_WAIT();   // bp of both CTAs ready

    if (tid < OUT) {
        uint32_t la = smbase + (uint32_t)(S_BP + slot * 64 + tid) * 4u;
        base[tid] = bias[tid] + bp[tid] + ld_peer_f32(la, peer);
    }
    __syncthreads();

    // emit + fused local colsum of this layer's output
    float* drow = D + n * STRIDE + j0;
    float r[JT];
    #pragma unroll
    for (int v = 0; v < JT / 2; v++) {
        float lo, hi; unpack2(acc2[v], lo, hi);
        r[2*v]   = fmaxf(base[j0 + 2*v]     - lo, 0.f);
        r[2*v+1] = fmaxf(base[j0 + 2*v + 1] - hi, 0.f);
    }
    if constexpr (JT == 8) {
        reinterpret_cast<float4*>(drow)[0] = make_float4(r[0], r[1], r[2], r[3]);
        reinterpret_cast<float4*>(drow)[1] = make_float4(r[4], r[5], r[6], r[7]);
    } else if constexpr (JT == 4) {
        *reinterpret_cast<float4*>(drow) = make_float4(r[0], r[1], r[2], r[3]);
    } else {
        *reinterpret_cast<float2*>(drow) = make_float2(r[0], r[1]);
    }
    #pragma unroll
    for (int off = 1; off < 32; off <<= 1) {
        #pragma unroll
        for (int v = 0; v < JT; v++)
            r[v] += __shfl_xor_sync(0xffffffffu, r[v], off);
    }
    if (lane == 0) {
        #pragma unroll
        for (int v = 0; v < JT; v++) atomicAdd(&cs_next[j0 + v], r[v]);
    }
    __syncthreads();
}

__global__ __launch_bounds__(THREADS, 1) __cluster_dims__(2, 1, 1)
void gnn_scene_kernel(const float* __restrict__ obj_info,
                      const float* __restrict__ W1, const float* __restrict__ b1,
                      const float* __restrict__ W2, const float* __restrict__ b2,
                      const float* __restrict__ W3, const float* __restrict__ b3,
                      const float* __restrict__ W4, const float* __restrict__ b4,
                      const float* __restrict__ Wn, const float* __restrict__ bn,
                      const float* __restrict__ Wg1, const float* __restrict__ bg1,
                      const float* __restrict__ Wg2, const float* __restrict__ bg2,
                      float* __restrict__ out) {
    extern __shared__ float sm[];
    const int tid  = threadIdx.x;
    const int lane = tid & 31;
    const int b    = blockIdx.x >> 1;
    const uint32_t rank = blockIdx.x & 1;
    const uint32_t peer = rank ^ 1u;
    const int n = tid & (LOCALN - 1);   // local node 0..63
    const int q = tid >> 6;             // 0..7
    const uint32_t smbase = smem_u32(sm);

    // ---- load + prescale weights (float4 where possible) ----
    {
        const float4* w14 = reinterpret_cast<const float4*>(W1);
        for (int i = tid; i < 80; i += THREADS) {
            float4 w = w14[i];
            reinterpret_cast<float4*>(sm + S_W1s)[i] =
                make_float4(w.x * INV127, w.y * INV127, w.z * INV127, w.w * INV127);
            const float s = 128.0f * INV127;
            reinterpret_cast<float4*>(sm + S_W1s128)[i] =
                make_float4(w.x * s, w.y * s, w.z * s, w.w * s);
        }
    }
    #define CPYS4(dst, src, cnt4) { \
        const float4* s4_ = reinterpret_cast<const float4*>(src); \
        for (int i = tid; i < (cnt4); i += THREADS) { \
            float4 w = s4_[i]; \
            reinterpret_cast<float4*>(sm + (dst))[i] = \
                make_float4(w.x * INV127, w.y * INV127, w.z * INV127, w.w * INV127); \
        } }
    #define CPY(dst, src, cnt) \
        for (int i = tid; i < (cnt); i += THREADS) sm[(dst) + i] = src[i];
    CPYS4(S_W2s, W2, 1200);  CPY(S_B2, b2, 64);
    CPYS4(S_W3s, W3, 512);   CPY(S_B3, b3, 32);
    CPYS4(S_W4s, W4, 128);   CPY(S_B4, b4, 16);
    for (int i = tid; i < 32; i += THREADS) sm[S_WNs + i] = Wn[i] * INV127;
    CPY(S_BN, bn, 2);
    CPY(S_B1, b1, 64);
    CPY(S_WG1, Wg1, 16*8);   CPY(S_BG1, bg1, 8);
    CPY(S_WG2, Wg2, 8);      CPY(S_BG2, bg2, 1);
    #undef CPYS4
    #undef CPY

    // ---- load this CTA's 64 rows of info[b] into A cols 64..74 ----
    {
        const float* src = obj_info + ((size_t)b * NODES + rank * LOCALN) * 11;
        for (int i = tid; i < LOCALN * 11; i += THREADS) {
            int r = i / 11, c = i % 11;
            sm[S_A + r * STRIDE + 64 + c] = src[i];
        }
    }
    // zero atomic-accumulated cs slots (all four, once)
    if (tid < 64)        sm[S_CS2 + tid] = 0.f;
    else if (tid < 128)  sm[S_CS3 + tid - 64] = 0.f;
    else if (tid < 160)  sm[S_CS4 + tid - 128] = 0.f;
    else if (tid < 176)  sm[S_CS5 + tid - 160] = 0.f;
    __syncthreads();

    float* A  = sm + S_A;
    float* Bb = sm + S_BUF;

    // ---- info colsum (11 cols x 64 rows) -> cs2[64..74] ----
    if (tid < 11 * 16) {
        int c = tid % 11, p = tid / 11;
        float s = 0.f;
        #pragma unroll
        for (int r = 0; r < 4; r++) s += A[(p * 4 + r) * STRIDE + 64 + c];
        sm[S_PART + p * 11 + c] = s;
    }
    __syncthreads();
    if (tid < 11) {
        float s = 0.f;
        #pragma unroll
        for (int p = 0; p < 16; p++) s += sm[S_PART + p * 11 + tid];
        sm[S_CS2 + 64 + tid] = s;
    }
    __syncthreads();

    // L1 (edge): info (A cols 64..68) -> h1 (A cols 0..63); colsum -> cs2[0..63]
    layer_run<5, 64, 8>(sm, A, 64, A, sm + S_CS2 + 64, sm + S_CS2,
                        sm + S_W1s, sm + S_W1s128, sm + S_B1,
                        0, tid, lane, n, q, peer, smbase);

    // L2: h75 (A cols 0..74; cs2[0..74]) -> h2 (Bb); colsum -> cs3
    layer_run<75, 64, 8>(sm, A, 0, Bb, sm + S_CS2, sm + S_CS3,
                         sm + S_W2s, sm + S_W2s, sm + S_B2,
                         1, tid, lane, n, q, peer, smbase);

    // L3: h2 -> h3 (A cols 0..31); colsum -> cs4
    layer_run<64, 32, 4>(sm, Bb, 0, A, sm + S_CS3, sm + S_CS4,
                         sm + S_W3s, sm + S_W3s, sm + S_B3,
                         0, tid, lane, n, q, peer, smbase);

    // L4: h3 -> h4 (Bb cols 0..15); colsum -> cs5
    layer_run<32, 16, 2>(sm, A, 0, Bb, sm + S_CS4, sm + S_CS5,
                         sm + S_W4s, sm + S_W4s, sm + S_B4,
                         1, tid, lane, n, q, peer, smbase);

    // ---- heads on h4 (Bb cols 0..15; local colsum = cs5) ----
    {
        float* base = sm + S_BASE;
        float* bp   = sm + S_BP;       // slot 0 (safe: L4 barrier passed)
        if (tid < 8) {
            int j = tid >> 2, p = tid & 3;
            float s = 0.f;
            for (int k = p; k < 16; k += 4) s += sm[S_CS5 + k] * sm[S_WNs + k * 2 + j];
            s += __shfl_xor_sync(0xffu, s, 1);
            s += __shfl_xor_sync(0xffu, s, 2);
            if (p == 0) bp[j] = s;
        }
        CLUSTER_ARRIVE();
        float accn = 0.f;
        if (q < 2) {
            const float* srow = Bb + n * STRIDE;
            #pragma unroll
            for (int k = 0; k < 16; k++) accn += srow[k] * sm[S_WNs + k * 2 + q];
        }
        CLUSTER_WAIT();
        if (tid < 2) {
            uint32_t la = smbase + (uint32_t)(S_BP + tid) * 4u;
            base[tid] = sm[S_BN + tid] + bp[tid] + ld_peer_f32(la, peer);
        } else if (tid >= 32 && tid < 48) {
            uint32_t la = smbase + (uint32_t)(S_CS5 + tid - 32) * 4u;
            sm[S_SCENEB + tid - 32] = ld_peer_f32(la, peer);
        }
        __syncthreads();
        if (q < 2) {
            size_t gnode = (size_t)b * NODES + rank * LOCALN + n;
            out[64 + gnode * 2 + q] = base[q] - accn;
        }

        // scene head: rank 0, thread 0
        if (rank == 0 && tid == 0) {
            float scene[16];
            #pragma unroll
            for (int k = 0; k < 16; k++)
                scene[k] = (sm[S_CS5 + k] + sm[S_SCENEB + k]) * (1.0f / NODES);
            float z = sm[S_BG2];
            #pragma unroll
            for (int o = 0; o < 8; o++) {
                float g = sm[S_BG1 + o];
                #pragma unroll
                for (int k = 0; k < 16; k++) g += scene[k] * sm[S_WG1 + k * 8 + o];
                g = fmaxf(g, 0.f);
                z += g * sm[S_WG2 + o];
            }
            out[b] = 1.0f / (1.0f + expf(-z));
        }
    }

    // no CTA may exit while the peer might still read its smem via DSMEM
    CLUSTER_ARRIVE();
    CLUSTER_WAIT();
}

extern "C" void kernel_launch(void* const* d_in, const int* in_sizes, int n_in,
                              void* d_out, int out_size) {
    const float* obj = (const float*)d_in[0];
    const float* W1  = (const float*)d_in[1];
    const float* b1  = (const float*)d_in[2];
    const float* W2  = (const float*)d_in[3];
    const float* b2  = (const float*)d_in[4];
    const float* W3  = (const float*)d_in[5];
    const float* b3  = (const float*)d_in[6];
    const float* W4  = (const float*)d_in[7];
    const float* b4  = (const float*)d_in[8];
    const float* Wn  = (const float*)d_in[9];
    const float* bn  = (const float*)d_in[10];
    const float* Wg1 = (const float*)d_in[11];
    const float* bg1 = (const float*)d_in[12];
    const float* Wg2 = (const float*)d_in[13];
    const float* bg2 = (const float*)d_in[14];
    // d_in[15]=src, d_in[16]=dst: complete graph, exploited analytically.

    cudaFuncSetAttribute(gnn_scene_kernel,
                         cudaFuncAttributeMaxDynamicSharedMemorySize, SMEM_BYTES);
    gnn_scene_kernel<<<SCENES * 2, THREADS, SMEM_BYTES>>>(
        obj, W1, b1, W2, b2, W3, b3, W4, b4, Wn, bn, Wg1, bg1, Wg2, bg2,
        (float*)d_out);
}

// round 12
// speedup vs baseline: 1.1481x; 1.1481x over previous
#include <cuda_runtime.h>
#include <math.h>
#include <stdint.h>

// GNN on complete per-scene digraphs: B=64 scenes, N=128 nodes.
// segment_mean at node d = (scene_sum(h) - h[d]) / 127.
// R12 = R10 frame (best, 18.6us: separate colsum pass, pull bp exchange,
// 2-CTA cluster/scene, 512 thr) with a new thread mapping:
//   lane n2 = tid&31 handles TWO nodes (n2, n2+32); q = tid>>5 picks one of
//   16 column groups (JT2 = OUT/16 = 4/4/2/1). Each weight float4 is now
//   loaded once per CTA (was twice) -> ~33% less LSU in the hot loop.
// Plus float4 weight prologue. Packed fma.rn.f32x2 throughout.

#define NODES    128
#define LOCALN   64
#define SCENES   64
#define THREADS  512
#define STRIDE   84
#define INV127   (1.0f/127.0f)

typedef unsigned long long u64;

// smem layout (float indices)
#define S_W1s    0            // 5*64  (W1/127)
#define S_W1s128 320          // 5*64  (W1*128/127)
#define S_B1     640          // 64
#define S_W2s    704          // 75*64
#define S_B2     5504         // 64
#define S_W3s    5568         // 64*32
#define S_B3     7616         // 32
#define S_W4s    7648         // 32*16
#define S_B4     8160         // 16
#define S_WNs    8176         // 16*2
#define S_BN     8208         // 2 (+2)
#define S_WG1    8212         // 16*8
#define S_BG1    8340         // 8
#define S_WG2    8348         // 8
#define S_BG2    8356         // 1 (+3)
#define S_A      8360         // 64*84
#define S_BUF    13736        // 64*84
#define S_CSL    19112        // 2 slots x 80 local colsums
#define S_BP     19272        // 2 slots x 64 base-partials
#define S_BASE   19400        // 64
#define S_SCENEB 19464        // 16
#define S_PART   19480        // 512
#define S_TOT    19992
#define SMEM_BYTES (S_TOT * 4)   // 79968 B

__device__ __forceinline__ uint32_t smem_u32(const void* p) {
    uint32_t a;
    asm("{ .reg .u64 t; cvta.to.shared.u64 t, %1; cvt.u32.u64 %0, t; }"
        : "=r"(a) : "l"(p));
    return a;
}
__device__ __forceinline__ float ld_peer_f32(uint32_t la, uint32_t peer) {
    uint32_t ra;
    asm("mapa.shared::cluster.u32 %0, %1, %2;" : "=r"(ra) : "r"(la), "r"(peer));
    float v;
    asm volatile("ld.shared::cluster.f32 %0, [%1];" : "=f"(v) : "r"(ra));
    return v;
}
#define CLUSTER_ARRIVE() asm volatile("barrier.cluster.arrive.aligned;" ::: "memory")
#define CLUSTER_WAIT()   asm volatile("barrier.cluster.wait.aligned;"   ::: "memory")

// ---- packed f32x2 helpers ----
__device__ __forceinline__ u64 pack2(float lo, float hi) {
    u64 r; asm("mov.b64 %0, {%1, %2};" : "=l"(r) : "f"(lo), "f"(hi)); return r;
}
__device__ __forceinline__ void unpack2(u64 v, float& lo, float& hi) {
    asm("mov.b64 {%0, %1}, %2;" : "=f"(lo), "=f"(hi) : "l"(v));
}
__device__ __forceinline__ u64 fma2(u64 a, u64 b, u64 c) {
    u64 r; asm("fma.rn.f32x2 %0, %1, %2, %3;" : "=l"(r) : "l"(a), "l"(b), "l"(c)); return r;
}

// local column sum over LOCALN rows of C columns at 'off' -> dst[C].
template<int C>
__device__ __forceinline__ void colsum_local(const float* __restrict__ S, int off,
                                             float* __restrict__ dst,
                                             float* __restrict__ part, int tid) {
    constexpr int P    = (THREADS / C) < 8 ? (THREADS / C) : 8;
    constexpr int ROWS = (LOCALN + P - 1) / P;
    if (tid < C * P) {
        int c = tid % C, p = tid / C;
        int r0 = p * ROWS;
        int r1 = (r0 + ROWS < LOCALN) ? (r0 + ROWS) : LOCALN;
        float s = 0.f;
        for (int r = r0; r < r1; r++) s += S[r * STRIDE + off + c];
        part[p * C + c] = s;
    }
    __syncthreads();
    if (tid < C) {
        float s = 0.f;
        #pragma unroll
        for (int p = 0; p < P; p++) s += part[p * C + tid];
        dst[tid] = s;
    }
    __syncthreads();
}

// one k-step of the 2-node packed node term
template<int OUT, int JT2>
__device__ __forceinline__ void nt2_step(float a, float b,
                                         const float* __restrict__ Ws,
                                         int k, int j0,
                                         u64* __restrict__ accA,
                                         u64* __restrict__ accB) {
    if constexpr (JT2 == 4) {
        ulonglong2 w = *reinterpret_cast<const ulonglong2*>(Ws + k * OUT + j0);
        u64 aa = pack2(a, a), bb = pack2(b, b);
        accA[0] = fma2(aa, w.x, accA[0]);
        accA[1] = fma2(aa, w.y, accA[1]);
        accB[0] = fma2(bb, w.x, accB[0]);
        accB[1] = fma2(bb, w.y, accB[1]);
    } else if constexpr (JT2 == 2) {
        u64 w = *reinterpret_cast<const u64*>(Ws + k * OUT + j0);
        accA[0] = fma2(pack2(a, a), w, accA[0]);
        accB[0] = fma2(pack2(b, b), w, accB[0]);
    } else {
        float w = Ws[k * OUT + j0];
        accA[0] = fma2(pack2(a, b), pack2(w, w), accA[0]);   // (nodeA, nodeB)
    }
}

// node term for two nodes (na, nb): accA/accB cover columns j0..j0+JT2-1
template<int IN, int OUT, int JT2>
__device__ __forceinline__ void nodeterm2(const float* __restrict__ S, int soff,
                                          const float* __restrict__ Ws,
                                          u64* __restrict__ accA,
                                          u64* __restrict__ accB,
                                          int na, int nb, int j0) {
    constexpr int NA = (JT2 == 4) ? 2 : 1;
    #pragma unroll
    for (int v = 0; v < NA; v++) { accA[v] = 0ull; accB[v] = 0ull; }
    const float4* sa4 = reinterpret_cast<const float4*>(S + na * STRIDE + soff);
    const float4* sb4 = reinterpret_cast<const float4*>(S + nb * STRIDE + soff);
    constexpr int KB = IN / 4;
    for (int kb = 0; kb < KB; kb++) {
        float4 a4 = sa4[kb], b4 = sb4[kb];
        nt2_step<OUT, JT2>(a4.x, b4.x, Ws, 4 * kb + 0, j0, accA, accB);
        nt2_step<OUT, JT2>(a4.y, b4.y, Ws, 4 * kb + 1, j0, accA, accB);
        nt2_step<OUT, JT2>(a4.z, b4.z, Ws, 4 * kb + 2, j0, accA, accB);
        nt2_step<OUT, JT2>(a4.w, b4.w, Ws, 4 * kb + 3, j0, accA, accB);
    }
    #pragma unroll
    for (int k = KB * 4; k < IN; k++) {
        float a = (S + na * STRIDE + soff)[k];
        float b = (S + nb * STRIDE + soff)[k];
        nt2_step<OUT, JT2>(a, b, Ws, k, j0, accA, accB);
    }
}

// One GCN layer, R10 sequence with the 2-node mapping:
//   colsum_local -> basepart(bp slot) -> ARRIVE -> nodeterm(2 nodes) -> WAIT ->
//   combine -> sync -> emit(2 nodes) -> sync
template<int IN, int OUT, int JT2>
__device__ __forceinline__ void layer_run(
    float* __restrict__ sm, const float* __restrict__ Ssrc, int soff,
    float* __restrict__ D, int csoff,
    const float* __restrict__ Wb, const float* __restrict__ Wn_,
    const float* __restrict__ bias,
    int slot, int tid, int na, int nb, int q, uint32_t peer, uint32_t smbase)
{
    float* base = sm + S_BASE;
    float* csl  = sm + S_CSL + slot * 80;
    float* bp   = sm + S_BP  + slot * 64;

    colsum_local<IN>(Ssrc, csoff, csl, sm + S_PART, tid);

    // base-partial on LOCAL colsum: 4 threads per output column
    if (tid < 4 * OUT) {
        const int j = tid >> 2, p = tid & 3;
        float s = 0.f;
        for (int k = p; k < IN; k += 4) s += csl[k] * Wb[k * OUT + j];
        s += __shfl_xor_sync(0xffffffffu, s, 1);
        s += __shfl_xor_sync(0xffffffffu, s, 2);
        if (p == 0) bp[j] = s;
    }
    CLUSTER_ARRIVE();

    const int j0 = q * JT2;
    u64 accA[(JT2 == 4) ? 2 : 1], accB[(JT2 == 4) ? 2 : 1];
    nodeterm2<IN, OUT, JT2>(Ssrc, soff, Wn_, accA, accB, na, nb, j0);

    CLUSTER_WAIT();

    if (tid < OUT) {
        uint32_t la = smbase + (uint32_t)(S_BP + slot * 64 + tid) * 4u;
        base[tid] = bias[tid] + bp[tid] + ld_peer_f32(la, peer);
    }
    __syncthreads();

    // emit: relu(base - acc) for both nodes
    float* da = D + na * STRIDE + j0;
    float* db = D + nb * STRIDE + j0;
    if constexpr (JT2 == 4) {
        float a0, a1, a2, a3, b0, b1, b2, b3;
        unpack2(accA[0], a0, a1); unpack2(accA[1], a2, a3);
        unpack2(accB[0], b0, b1); unpack2(accB[1], b2, b3);
        float c0 = base[j0], c1 = base[j0+1], c2 = base[j0+2], c3 = base[j0+3];
        *reinterpret_cast<float4*>(da) = make_float4(
            fmaxf(c0 - a0, 0.f), fmaxf(c1 - a1, 0.f),
            fmaxf(c2 - a2, 0.f), fmaxf(c3 - a3, 0.f));
        *reinterpret_cast<float4*>(db) = make_float4(
            fmaxf(c0 - b0, 0.f), fmaxf(c1 - b1, 0.f),
            fmaxf(c2 - b2, 0.f), fmaxf(c3 - b3, 0.f));
    } else if constexpr (JT2 == 2) {
        float a0, a1, b0, b1;
        unpack2(accA[0], a0, a1); unpack2(accB[0], b0, b1);
        float c0 = base[j0], c1 = base[j0+1];
        *reinterpret_cast<float2*>(da) = make_float2(fmaxf(c0 - a0, 0.f), fmaxf(c1 - a1, 0.f));
        *reinterpret_cast<float2*>(db) = make_float2(fmaxf(c0 - b0, 0.f), fmaxf(c1 - b1, 0.f));
    } else {
        float va, vb;
        unpack2(accA[0], va, vb);
        float c0 = base[j0];
        da[0] = fmaxf(c0 - va, 0.f);
        db[0] = fmaxf(c0 - vb, 0.f);
    }
    __syncthreads();
}

__global__ __launch_bounds__(THREADS, 1) __cluster_dims__(2, 1, 1)
void gnn_scene_kernel(const float* __restrict__ obj_info,
                      const float* __restrict__ W1, const float* __restrict__ b1,
                      const float* __restrict__ W2, const float* __restrict__ b2,
                      const float* __restrict__ W3, const float* __restrict__ b3,
                      const float* __restrict__ W4, const float* __restrict__ b4,
                      const float* __restrict__ Wn, const float* __restrict__ bn,
                      const float* __restrict__ Wg1, const float* __restrict__ bg1,
                      const float* __restrict__ Wg2, const float* __restrict__ bg2,
                      float* __restrict__ out) {
    extern __shared__ float sm[];
    const int tid  = threadIdx.x;
    const int b    = blockIdx.x >> 1;
    const uint32_t rank = blockIdx.x & 1;
    const uint32_t peer = rank ^ 1u;
    const int na = tid & 31;            // node a (0..31)
    const int nb = na + 32;             // node b (32..63)
    const int q  = tid >> 5;            // column group 0..15
    const uint32_t smbase = smem_u32(sm);

    // ---- load + prescale weights (float4) ----
    {
        const float4* w14 = reinterpret_cast<const float4*>(W1);
        for (int i = tid; i < 80; i += THREADS) {
            float4 w = w14[i];
            reinterpret_cast<float4*>(sm + S_W1s)[i] =
                make_float4(w.x * INV127, w.y * INV127, w.z * INV127, w.w * INV127);
            const float s = 128.0f * INV127;
            reinterpret_cast<float4*>(sm + S_W1s128)[i] =
                make_float4(w.x * s, w.y * s, w.z * s, w.w * s);
        }
    }
    #define CPYS4(dst, src, cnt4) { \
        const float4* s4_ = reinterpret_cast<const float4*>(src); \
        for (int i = tid; i < (cnt4); i += THREADS) { \
            float4 w = s4_[i]; \
            reinterpret_cast<float4*>(sm + (dst))[i] = \
                make_float4(w.x * INV127, w.y * INV127, w.z * INV127, w.w * INV127); \
        } }
    #define CPY(dst, src, cnt) \
        for (int i = tid; i < (cnt); i += THREADS) sm[(dst) + i] = src[i];
    CPYS4(S_W2s, W2, 1200);  CPY(S_B2, b2, 64);
    CPYS4(S_W3s, W3, 512);   CPY(S_B3, b3, 32);
    CPYS4(S_W4s, W4, 128);   CPY(S_B4, b4, 16);
    for (int i = tid; i < 32; i += THREADS) sm[S_WNs + i] = Wn[i] * INV127;
    CPY(S_BN, bn, 2);
    CPY(S_B1, b1, 64);
    CPY(S_WG1, Wg1, 16*8);   CPY(S_BG1, bg1, 8);
    CPY(S_WG2, Wg2, 8);      CPY(S_BG2, bg2, 1);
    #undef CPYS4
    #undef CPY

    // ---- load this CTA's 64 rows of info[b] into A cols 64..74 ----
    {
        const float* src = obj_info + ((size_t)b * NODES + rank * LOCALN) * 11;
        for (int i = tid; i < LOCALN * 11; i += THREADS) {
            int r = i / 11, c = i % 11;
            sm[S_A + r * STRIDE + 64 + c] = src[i];
        }
    }
    __syncthreads();

    float* A  = sm + S_A;
    float* Bb = sm + S_BUF;

    // L1 (edge): info (A cols 64..68) -> h1 (A cols 0..63)
    layer_run<5, 64, 4>(sm, A, 64, A, 64,
                        sm + S_W1s, sm + S_W1s128, sm + S_B1,
                        0, tid, na, nb, q, peer, smbase);

    // L2: h75 (A cols 0..74) -> h2 (Bb cols 0..63)
    layer_run<75, 64, 4>(sm, A, 0, Bb, 0,
                         sm + S_W2s, sm + S_W2s, sm + S_B2,
                         1, tid, na, nb, q, peer, smbase);

    // L3: h2 -> h3 (A cols 0..31)
    layer_run<64, 32, 2>(sm, Bb, 0, A, 0,
                         sm + S_W3s, sm + S_W3s, sm + S_B3,
                         0, tid, na, nb, q, peer, smbase);

    // L4: h3 -> h4 (Bb cols 0..15)
    layer_run<32, 16, 1>(sm, A, 0, Bb, 0,
                         sm + S_W4s, sm + S_W4s, sm + S_B4,
                         1, tid, na, nb, q, peer, smbase);

    // ---- heads on h4 (Bb cols 0..15) ----
    {
        float* base = sm + S_BASE;
        float* csl  = sm + S_CSL;      // slot 0
        float* bp   = sm + S_BP;       // slot 0
        colsum_local<16>(Bb, 0, csl, sm + S_PART, tid);

        if (tid < 8) {
            int j = tid >> 2, p = tid & 3;
            float s = 0.f;
            for (int k = p; k < 16; k += 4) s += csl[k] * sm[S_WNs + k * 2 + j];
            s += __shfl_xor_sync(0xffu, s, 1);
            s += __shfl_xor_sync(0xffu, s, 2);
            if (p == 0) bp[j] = s;
        }
        CLUSTER_ARRIVE();
        float accnA = 0.f, accnB = 0.f;
        if (q < 2) {   // tid < 64: column j=q for both nodes
            const float* sa = Bb + na * STRIDE;
            const float* sb = Bb + nb * STRIDE;
            #pragma unroll
            for (int k = 0; k < 16; k++) {
                float w = sm[S_WNs + k * 2 + q];
                accnA += sa[k] * w;
                accnB += sb[k] * w;
            }
        }
        CLUSTER_WAIT();
        if (tid < 2) {
            uint32_t la = smbase + (uint32_t)(S_BP + tid) * 4u;
            base[tid] = sm[S_BN + tid] + bp[tid] + ld_peer_f32(la, peer);
        } else if (tid >= 32 && tid < 48) {
            uint32_t la = smbase + (uint32_t)(S_CSL + tid - 32) * 4u;
            sm[S_SCENEB + tid - 32] = ld_peer_f32(la, peer);
        }
        __syncthreads();
        if (q < 2) {
            size_t g0 = (size_t)b * NODES + rank * LOCALN;
            out[64 + (g0 + na) * 2 + q] = base[q] - accnA;
            out[64 + (g0 + nb) * 2 + q] = base[q] - accnB;
        }

        // scene head: rank 0, thread 0
        if (rank == 0 && tid == 0) {
            float scene[16];
            #pragma unroll
            for (int k = 0; k < 16; k++)
                scene[k] = (csl[k] + sm[S_SCENEB + k]) * (1.0f / NODES);
            float z = sm[S_BG2];
            #pragma unroll
            for (int o = 0; o < 8; o++) {
                float g = sm[S_BG1 + o];
                #pragma unroll
                for (int k = 0; k < 16; k++) g += scene[k] * sm[S_WG1 + k * 8 + o];
                g = fmaxf(g, 0.f);
                z += g * sm[S_WG2 + o];
            }
            out[b] = 1.0f / (1.0f + expf(-z));
        }
    }

    // no CTA may exit while the peer might still read its smem via DSMEM
    CLUSTER_ARRIVE();
    CLUSTER_WAIT();
}

extern "C" void kernel_launch(void* const* d_in, const int* in_sizes, int n_in,
                              void* d_out, int out_size) {
    const float* obj = (const float*)d_in[0];
    const float* W1  = (const float*)d_in[1];
    const float* b1  = (const float*)d_in[2];
    const float* W2  = (const float*)d_in[3];
    const float* b2  = (const float*)d_in[4];
    const float* W3  = (const float*)d_in[5];
    const float* b3  = (const float*)d_in[6];
    const float* W4  = (const float*)d_in[7];
    const float* b4  = (const float*)d_in[8];
    const float* Wn  = (const float*)d_in[9];
    const float* bn  = (const float*)d_in[10];
    const float* Wg1 = (const float*)d_in[11];
    const float* bg1 = (const float*)d_in[12];
    const float* Wg2 = (const float*)d_in[13];
    const float* bg2 = (const float*)d_in[14];
    // d_in[15]=src, d_in[16]=dst: complete graph, exploited analytically.

    cudaFuncSetAttribute(gnn_scene_kernel,
                         cudaFuncAttributeMaxDynamicSharedMemorySize, SMEM_BYTES);
    gnn_scene_kernel<<<SCENES * 2, THREADS, SMEM_BYTES>>>(
        obj, W1, b1, W2, b2, W3, b3, W4, b4, Wn, bn, Wg1, bg1, Wg2, bg2,
        (float*)d_out);
}

// round 13
// speedup vs baseline: 1.1547x; 1.0058x over previous
#include <cuda_runtime.h>
#include <math.h>
#include <stdint.h>

// GNN on complete per-scene digraphs: B=64 scenes, N=128 nodes.
// segment_mean at node d = (scene_sum(h) - h[d]) / 127.
// R13 = R12 (best, 16.6us) + per-warp combine:
//   after CLUSTER_WAIT, lanes 0..JT2-1 of each warp compute their own
//   base[j] = bias + bp_local + bp_peer (DSMEM) and shfl-broadcast.
//   Removes 1 __syncthreads/layer, the base[] smem round trip, and the
//   heads-section sync. Mapping unchanged: lane handles nodes (n2, n2+32),
//   q = tid>>5 picks 1 of 16 column groups (JT2 = 4/4/2/1), each weight
//   float4 loaded once per CTA. Packed fma.rn.f32x2, STRIDE=84 float4 rows.

#define NODES    128
#define LOCALN   64
#define SCENES   64
#define THREADS  512
#define STRIDE   84
#define INV127   (1.0f/127.0f)

typedef unsigned long long u64;

// smem layout (float indices)
#define S_W1s    0            // 5*64  (W1/127)
#define S_W1s128 320          // 5*64  (W1*128/127)
#define S_B1     640          // 64
#define S_W2s    704          // 75*64
#define S_B2     5504         // 64
#define S_W3s    5568         // 64*32
#define S_B3     7616         // 32
#define S_W4s    7648         // 32*16
#define S_B4     8160         // 16
#define S_WNs    8176         // 16*2
#define S_BN     8208         // 2 (+2)
#define S_WG1    8212         // 16*8
#define S_BG1    8340         // 8
#define S_WG2    8348         // 8
#define S_BG2    8356         // 1 (+3)
#define S_A      8360         // 64*84
#define S_BUF    13736        // 64*84
#define S_CSL    19112        // 2 slots x 80 local colsums
#define S_BP     19272        // 2 slots x 64 base-partials
#define S_PART   19400        // 512
#define S_TOT    19912
#define SMEM_BYTES (S_TOT * 4)   // 79648 B

__device__ __forceinline__ uint32_t smem_u32(const void* p) {
    uint32_t a;
    asm("{ .reg .u64 t; cvta.to.shared.u64 t, %1; cvt.u32.u64 %0, t; }"
        : "=r"(a) : "l"(p));
    return a;
}
__device__ __forceinline__ float ld_peer_f32(uint32_t la, uint32_t peer) {
    uint32_t ra;
    asm("mapa.shared::cluster.u32 %0, %1, %2;" : "=r"(ra) : "r"(la), "r"(peer));
    float v;
    asm volatile("ld.shared::cluster.f32 %0, [%1];" : "=f"(v) : "r"(ra));
    return v;
}
#define CLUSTER_ARRIVE() asm volatile("barrier.cluster.arrive.aligned;" ::: "memory")
#define CLUSTER_WAIT()   asm volatile("barrier.cluster.wait.aligned;"   ::: "memory")

// ---- packed f32x2 helpers ----
__device__ __forceinline__ u64 pack2(float lo, float hi) {
    u64 r; asm("mov.b64 %0, {%1, %2};" : "=l"(r) : "f"(lo), "f"(hi)); return r;
}
__device__ __forceinline__ void unpack2(u64 v, float& lo, float& hi) {
    asm("mov.b64 {%0, %1}, %2;" : "=f"(lo), "=f"(hi) : "l"(v));
}
__device__ __forceinline__ u64 fma2(u64 a, u64 b, u64 c) {
    u64 r; asm("fma.rn.f32x2 %0, %1, %2, %3;" : "=l"(r) : "l"(a), "l"(b), "l"(c)); return r;
}

// local column sum over LOCALN rows of C columns at 'off' -> dst[C].
template<int C>
__device__ __forceinline__ void colsum_local(const float* __restrict__ S, int off,
                                             float* __restrict__ dst,
                                             float* __restrict__ part, int tid) {
    constexpr int P    = (THREADS / C) < 8 ? (THREADS / C) : 8;
    constexpr int ROWS = (LOCALN + P - 1) / P;
    if (tid < C * P) {
        int c = tid % C, p = tid / C;
        int r0 = p * ROWS;
        int r1 = (r0 + ROWS < LOCALN) ? (r0 + ROWS) : LOCALN;
        float s = 0.f;
        for (int r = r0; r < r1; r++) s += S[r * STRIDE + off + c];
        part[p * C + c] = s;
    }
    __syncthreads();
    if (tid < C) {
        float s = 0.f;
        #pragma unroll
        for (int p = 0; p < P; p++) s += part[p * C + tid];
        dst[tid] = s;
    }
    __syncthreads();
}

// one k-step of the 2-node packed node term
template<int OUT, int JT2>
__device__ __forceinline__ void nt2_step(float a, float b,
                                         const float* __restrict__ Ws,
                                         int k, int j0,
                                         u64* __restrict__ accA,
                                         u64* __restrict__ accB) {
    if constexpr (JT2 == 4) {
        ulonglong2 w = *reinterpret_cast<const ulonglong2*>(Ws + k * OUT + j0);
        u64 aa = pack2(a, a), bb = pack2(b, b);
        accA[0] = fma2(aa, w.x, accA[0]);
        accA[1] = fma2(aa, w.y, accA[1]);
        accB[0] = fma2(bb, w.x, accB[0]);
        accB[1] = fma2(bb, w.y, accB[1]);
    } else if constexpr (JT2 == 2) {
        u64 w = *reinterpret_cast<const u64*>(Ws + k * OUT + j0);
        accA[0] = fma2(pack2(a, a), w, accA[0]);
        accB[0] = fma2(pack2(b, b), w, accB[0]);
    } else {
        float w = Ws[k * OUT + j0];
        accA[0] = fma2(pack2(a, b), pack2(w, w), accA[0]);   // (nodeA, nodeB)
    }
}

// node term for two nodes (na, nb): accA/accB cover columns j0..j0+JT2-1
template<int IN, int OUT, int JT2>
__device__ __forceinline__ void nodeterm2(const float* __restrict__ S, int soff,
                                          const float* __restrict__ Ws,
                                          u64* __restrict__ accA,
                                          u64* __restrict__ accB,
                                          int na, int nb, int j0) {
    constexpr int NA = (JT2 == 4) ? 2 : 1;
    #pragma unroll
    for (int v = 0; v < NA; v++) { accA[v] = 0ull; accB[v] = 0ull; }
    const float4* sa4 = reinterpret_cast<const float4*>(S + na * STRIDE + soff);
    const float4* sb4 = reinterpret_cast<const float4*>(S + nb * STRIDE + soff);
    constexpr int KB = IN / 4;
    for (int kb = 0; kb < KB; kb++) {
        float4 a4 = sa4[kb], b4 = sb4[kb];
        nt2_step<OUT, JT2>(a4.x, b4.x, Ws, 4 * kb + 0, j0, accA, accB);
        nt2_step<OUT, JT2>(a4.y, b4.y, Ws, 4 * kb + 1, j0, accA, accB);
        nt2_step<OUT, JT2>(a4.z, b4.z, Ws, 4 * kb + 2, j0, accA, accB);
        nt2_step<OUT, JT2>(a4.w, b4.w, Ws, 4 * kb + 3, j0, accA, accB);
    }
    #pragma unroll
    for (int k = KB * 4; k < IN; k++) {
        float a = (S + na * STRIDE + soff)[k];
        float b = (S + nb * STRIDE + soff)[k];
        nt2_step<OUT, JT2>(a, b, Ws, k, j0, accA, accB);
    }
}

// One GCN layer:
//   colsum_local -> basepart(bp slot) -> ARRIVE -> nodeterm(2 nodes) -> WAIT ->
//   per-warp combine (lanes 0..JT2-1 + shfl broadcast) -> emit -> sync
template<int IN, int OUT, int JT2>
__device__ __forceinline__ void layer_run(
    float* __restrict__ sm, const float* __restrict__ Ssrc, int soff,
    float* __restrict__ D, int csoff,
    const float* __restrict__ Wb, const float* __restrict__ Wn_,
    const float* __restrict__ bias,
    int slot, int tid, int lane, int na, int nb, int q,
    uint32_t peer, uint32_t smbase)
{
    float* csl = sm + S_CSL + slot * 80;
    float* bp  = sm + S_BP  + slot * 64;

    colsum_local<IN>(Ssrc, csoff, csl, sm + S_PART, tid);

    // base-partial on LOCAL colsum: 4 threads per output column
    if (tid < 4 * OUT) {
        const int j = tid >> 2, p = tid & 3;
        float s = 0.f;
        for (int k = p; k < IN; k += 4) s += csl[k] * Wb[k * OUT + j];
        s += __shfl_xor_sync(0xffffffffu, s, 1);
        s += __shfl_xor_sync(0xffffffffu, s, 2);
        if (p == 0) bp[j] = s;
    }
    CLUSTER_ARRIVE();

    const int j0 = q * JT2;
    u64 accA[(JT2 == 4) ? 2 : 1], accB[(JT2 == 4) ? 2 : 1];
    nodeterm2<IN, OUT, JT2>(Ssrc, soff, Wn_, accA, accB, na, nb, j0);

    CLUSTER_WAIT();   // acquire: local + peer bp visible to every thread

    // per-warp combine: lanes 0..JT2-1 compute base[j0+lane], broadcast
    float bmine = 0.f;
    if (lane < JT2) {
        int j = j0 + lane;
        uint32_t la = smbase + (uint32_t)(S_BP + slot * 64 + j) * 4u;
        bmine = bias[j] + bp[j] + ld_peer_f32(la, peer);
    }
    float c0 = __shfl_sync(0xffffffffu, bmine, 0);
    float c1 = (JT2 >= 2) ? __shfl_sync(0xffffffffu, bmine, 1) : 0.f;
    float c2 = (JT2 >= 4) ? __shfl_sync(0xffffffffu, bmine, 2) : 0.f;
    float c3 = (JT2 >= 4) ? __shfl_sync(0xffffffffu, bmine, 3) : 0.f;

    // emit: relu(base - acc) for both nodes
    float* da = D + na * STRIDE + j0;
    float* db = D + nb * STRIDE + j0;
    if constexpr (JT2 == 4) {
        float a0, a1, a2, a3, b0, b1, b2, b3;
        unpack2(accA[0], a0, a1); unpack2(accA[1], a2, a3);
        unpack2(accB[0], b0, b1); unpack2(accB[1], b2, b3);
        *reinterpret_cast<float4*>(da) = make_float4(
            fmaxf(c0 - a0, 0.f), fmaxf(c1 - a1, 0.f),
            fmaxf(c2 - a2, 0.f), fmaxf(c3 - a3, 0.f));
        *reinterpret_cast<float4*>(db) = make_float4(
            fmaxf(c0 - b0, 0.f), fmaxf(c1 - b1, 0.f),
            fmaxf(c2 - b2, 0.f), fmaxf(c3 - b3, 0.f));
    } else if constexpr (JT2 == 2) {
        float a0, a1, b0, b1;
        unpack2(accA[0], a0, a1); unpack2(accB[0], b0, b1);
        *reinterpret_cast<float2*>(da) = make_float2(fmaxf(c0 - a0, 0.f), fmaxf(c1 - a1, 0.f));
        *reinterpret_cast<float2*>(db) = make_float2(fmaxf(c0 - b0, 0.f), fmaxf(c1 - b1, 0.f));
    } else {
        float va, vb;
        unpack2(accA[0], va, vb);
        da[0] = fmaxf(c0 - va, 0.f);
        db[0] = fmaxf(c0 - vb, 0.f);
    }
    __syncthreads();   // D complete before next layer's colsum
}

__global__ __launch_bounds__(THREADS, 1) __cluster_dims__(2, 1, 1)
void gnn_scene_kernel(const float* __restrict__ obj_info,
                      const float* __restrict__ W1, const float* __restrict__ b1,
                      const float* __restrict__ W2, const float* __restrict__ b2,
                      const float* __restrict__ W3, const float* __restrict__ b3,
                      const float* __restrict__ W4, const float* __restrict__ b4,
                      const float* __restrict__ Wn, const float* __restrict__ bn,
                      const float* __restrict__ Wg1, const float* __restrict__ bg1,
                      const float* __restrict__ Wg2, const float* __restrict__ bg2,
                      float* __restrict__ out) {
    extern __shared__ float sm[];
    const int tid  = threadIdx.x;
    const int lane = tid & 31;
    const int b    = blockIdx.x >> 1;
    const uint32_t rank = blockIdx.x & 1;
    const uint32_t peer = rank ^ 1u;
    const int na = tid & 31;            // node a (0..31)
    const int nb = na + 32;             // node b (32..63)
    const int q  = tid >> 5;            // column group 0..15
    const uint32_t smbase = smem_u32(sm);

    // ---- load + prescale weights (float4) ----
    {
        const float4* w14 = reinterpret_cast<const float4*>(W1);
        for (int i = tid; i < 80; i += THREADS) {
            float4 w = w14[i];
            reinterpret_cast<float4*>(sm + S_W1s)[i] =
                make_float4(w.x * INV127, w.y * INV127, w.z * INV127, w.w * INV127);
            const float s = 128.0f * INV127;
            reinterpret_cast<float4*>(sm + S_W1s128)[i] =
                make_float4(w.x * s, w.y * s, w.z * s, w.w * s);
        }
    }
    #define CPYS4(dst, src, cnt4) { \
        const float4* s4_ = reinterpret_cast<const float4*>(src); \
        for (int i = tid; i < (cnt4); i += THREADS) { \
            float4 w = s4_[i]; \
            reinterpret_cast<float4*>(sm + (dst))[i] = \
                make_float4(w.x * INV127, w.y * INV127, w.z * INV127, w.w * INV127); \
        } }
    #define CPY(dst, src, cnt) \
        for (int i = tid; i < (cnt); i += THREADS) sm[(dst) + i] = src[i];
    CPYS4(S_W2s, W2, 1200);  CPY(S_B2, b2, 64);
    CPYS4(S_W3s, W3, 512);   CPY(S_B3, b3, 32);
    CPYS4(S_W4s, W4, 128);   CPY(S_B4, b4, 16);
    for (int i = tid; i < 32; i += THREADS) sm[S_WNs + i] = Wn[i] * INV127;
    CPY(S_BN, bn, 2);
    CPY(S_B1, b1, 64);
    CPY(S_WG1, Wg1, 16*8);   CPY(S_BG1, bg1, 8);
    CPY(S_WG2, Wg2, 8);      CPY(S_BG2, bg2, 1);
    #undef CPYS4
    #undef CPY

    // ---- load this CTA's 64 rows of info[b] into A cols 64..74 ----
    {
        const float* src = obj_info + ((size_t)b * NODES + rank * LOCALN) * 11;
        for (int i = tid; i < LOCALN * 11; i += THREADS) {
            int r = i / 11, c = i % 11;
            sm[S_A + r * STRIDE + 64 + c] = src[i];
        }
    }
    __syncthreads();

    float* A  = sm + S_A;
    float* Bb = sm + S_BUF;

    // L1 (edge): info (A cols 64..68) -> h1 (A cols 0..63)
    layer_run<5, 64, 4>(sm, A, 64, A, 64,
                        sm + S_W1s, sm + S_W1s128, sm + S_B1,
                        0, tid, lane, na, nb, q, peer, smbase);

    // L2: h75 (A cols 0..74) -> h2 (Bb cols 0..63)
    layer_run<75, 64, 4>(sm, A, 0, Bb, 0,
                         sm + S_W2s, sm + S_W2s, sm + S_B2,
                         1, tid, lane, na, nb, q, peer, smbase);

    // L3: h2 -> h3 (A cols 0..31)
    layer_run<64, 32, 2>(sm, Bb, 0, A, 0,
                         sm + S_W3s, sm + S_W3s, sm + S_B3,
                         0, tid, lane, na, nb, q, peer, smbase);

    // L4: h3 -> h4 (Bb cols 0..15)
    layer_run<32, 16, 1>(sm, A, 0, Bb, 0,
                         sm + S_W4s, sm + S_W4s, sm + S_B4,
                         1, tid, lane, na, nb, q, peer, smbase);

    // ---- heads on h4 (Bb cols 0..15) ----
    {
        float* csl = sm + S_CSL;      // slot 0
        float* bp  = sm + S_BP;       // slot 0
        colsum_local<16>(Bb, 0, csl, sm + S_PART, tid);

        if (tid < 8) {
            int j = tid >> 2, p = tid & 3;
            float s = 0.f;
            for (int k = p; k < 16; k += 4) s += csl[k] * sm[S_WNs + k * 2 + j];
            s += __shfl_xor_sync(0xffu, s, 1);
            s += __shfl_xor_sync(0xffu, s, 2);
            if (p == 0) bp[j] = s;
        }
        CLUSTER_ARRIVE();
        float accnA = 0.f, accnB = 0.f;
        if (q < 2) {   // warps 0,1: column j=q for both nodes
            const float* sa = Bb + na * STRIDE;
            const float* sb = Bb + nb * STRIDE;
            #pragma unroll
            for (int k = 0; k < 16; k++) {
                float w = sm[S_WNs + k * 2 + q];
                accnA += sa[k] * w;
                accnB += sb[k] * w;
            }
        }
        CLUSTER_WAIT();
        if (q < 2) {
            float baseq = 0.f;
            if (lane == 0) {
                uint32_t la = smbase + (uint32_t)(S_BP + q) * 4u;
                baseq = sm[S_BN + q] + bp[q] + ld_peer_f32(la, peer);
            }
            baseq = __shfl_sync(0xffffffffu, baseq, 0);
            size_t g0 = (size_t)b * NODES + rank * LOCALN;
            out[64 + (g0 + na) * 2 + q] = baseq - accnA;
            out[64 + (g0 + nb) * 2 + q] = baseq - accnB;
        }

        // scene head: rank 0, thread 0 pulls peer cs5 itself (no block sync)
        if (rank == 0 && tid == 0) {
            float scene[16];
            #pragma unroll
            for (int k = 0; k < 16; k++) {
                uint32_t la = smbase + (uint32_t)(S_CSL + k) * 4u;
                scene[k] = (csl[k] + ld_peer_f32(la, peer)) * (1.0f / NODES);
            }
            float z = sm[S_BG2];
            #pragma unroll
            for (int o = 0; o < 8; o++) {
                float g = sm[S_BG1 + o];
                #pragma unroll
                for (int k = 0; k < 16; k++) g += scene[k] * sm[S_WG1 + k * 8 + o];
                g = fmaxf(g, 0.f);
                z += g * sm[S_WG2 + o];
            }
            out[b] = 1.0f / (1.0f + expf(-z));
        }
    }

    // no CTA may exit while the peer might still read its smem via DSMEM
    CLUSTER_ARRIVE();
    CLUSTER_WAIT();
}

extern "C" void kernel_launch(void* const* d_in, const int* in_sizes, int n_in,
                              void* d_out, int out_size) {
    const float* obj = (const float*)d_in[0];
    const float* W1  = (const float*)d_in[1];
    const float* b1  = (const float*)d_in[2];
    const float* W2  = (const float*)d_in[3];
    const float* b2  = (const float*)d_in[4];
    const float* W3  = (const float*)d_in[5];
    const float* b3  = (const float*)d_in[6];
    const float* W4  = (const float*)d_in[7];
    const float* b4  = (const float*)d_in[8];
    const float* Wn  = (const float*)d_in[9];
    const float* bn  = (const float*)d_in[10];
    const float* Wg1 = (const float*)d_in[11];
    const float* bg1 = (const float*)d_in[12];
    const float* Wg2 = (const float*)d_in[13];
    const float* bg2 = (const float*)d_in[14];
    // d_in[15]=src, d_in[16]=dst: complete graph, exploited analytically.

    cudaFuncSetAttribute(gnn_scene_kernel,
                         cudaFuncAttributeMaxDynamicSharedMemorySize, SMEM_BYTES);
    gnn_scene_kernel<<<SCENES * 2, THREADS, SMEM_BYTES>>>(
        obj, W1, b1, W2, b2, W3, b3, W4, b4, Wn, bn, Wg1, bg1, Wg2, bg2,
        (float*)d_out);
}

// round 15
// speedup vs baseline: 1.1637x; 1.0078x over previous
#include <cuda_runtime.h>
#include <math.h>
#include <stdint.h>

// GNN on complete per-scene digraphs: B=64 scenes, N=128 nodes.
// segment_mean at node d = (scene_sum(h) - h[d]) / 127.
// R15 = R14 with redux.f32 (not available on sm_100) replaced by a packed
// f32x2 butterfly warp reduction. Colsum PASS stays deleted:
//   each warp owns its output columns exclusively and its lanes cover all
//   64 local rows -> next layer's local colsum = warp reduction of emitted
//   activations; lane0 stores directly (no atomics, no partials).
// Per layer: 1 __syncthreads + 1 cluster barrier.
// Mapping: lane handles nodes (lane, lane+32); q = tid>>5 -> 1 of 16 column
// groups (JT2 = 4/4/2/1); weights loaded once per CTA; fma.rn.f32x2;
// STRIDE=84 float4 rows; pull-style bp exchange, ping-pong slots.

#define NODES    128
#define LOCALN   64
#define SCENES   64
#define THREADS  512
#define STRIDE   84
#define INV127   (1.0f/127.0f)

typedef unsigned long long u64;

// smem layout (float indices)
#define S_W1s    0            // 5*64  (W1/127)
#define S_W1s128 320          // 5*64  (W1*128/127)
#define S_B1     640          // 64
#define S_W2s    704          // 75*64
#define S_B2     5504         // 64
#define S_W3s    5568         // 64*32
#define S_B3     7616         // 32
#define S_W4s    7648         // 32*16
#define S_B4     8160         // 16
#define S_WNs    8176         // 16*2
#define S_BN     8208         // 2 (+2)
#define S_WG1    8212         // 16*8
#define S_BG1    8340         // 8
#define S_WG2    8348         // 8
#define S_BG2    8356         // 1 (+3)
#define S_A      8360         // 64*84
#define S_BUF    13736        // 64*84
#define S_CS2    19112        // 80: [0..63] L1 colsum, [64..74] info colsum
#define S_CS3    19192        // 64 (L2)
#define S_CS4    19256        // 32 (L3)
#define S_CS5    19288        // 16 (L4)
#define S_BP     19304        // 2 slots x 64 base-partials
#define S_PART   19432        // 176 (info colsum partials)
#define S_TOT    19608
#define SMEM_BYTES (S_TOT * 4)   // 78432 B

__device__ __forceinline__ uint32_t smem_u32(const void* p) {
    uint32_t a;
    asm("{ .reg .u64 t; cvta.to.shared.u64 t, %1; cvt.u32.u64 %0, t; }"
        : "=r"(a) : "l"(p));
    return a;
}
__device__ __forceinline__ float ld_peer_f32(uint32_t la, uint32_t peer) {
    uint32_t ra;
    asm("mapa.shared::cluster.u32 %0, %1, %2;" : "=r"(ra) : "r"(la), "r"(peer));
    float v;
    asm volatile("ld.shared::cluster.f32 %0, [%1];" : "=f"(v) : "r"(ra));
    return v;
}
#define CLUSTER_ARRIVE() asm volatile("barrier.cluster.arrive.aligned;" ::: "memory")
#define CLUSTER_WAIT()   asm volatile("barrier.cluster.wait.aligned;"   ::: "memory")

// ---- packed f32x2 helpers ----
__device__ __forceinline__ u64 pack2(float lo, float hi) {
    u64 r; asm("mov.b64 %0, {%1, %2};" : "=l"(r) : "f"(lo), "f"(hi)); return r;
}
__device__ __forceinline__ void unpack2(u64 v, float& lo, float& hi) {
    asm("mov.b64 {%0, %1}, %2;" : "=f"(lo), "=f"(hi) : "l"(v));
}
__device__ __forceinline__ u64 add2(u64 a, u64 b) {
    u64 r; asm("add.rn.f32x2 %0, %1, %2;" : "=l"(r) : "l"(a), "l"(b)); return r;
}
__device__ __forceinline__ u64 fma2(u64 a, u64 b, u64 c) {
    u64 r; asm("fma.rn.f32x2 %0, %1, %2, %3;" : "=l"(r) : "l"(a), "l"(b), "l"(c)); return r;
}
// packed butterfly warp-sum of a u64 (two f32 lanes summed independently)
__device__ __forceinline__ u64 warpsum2(u64 v) {
    #pragma unroll
    for (int off = 16; off > 0; off >>= 1)
        v = add2(v, __shfl_xor_sync(0xffffffffu, v, off));
    return v;
}

// one k-step of the 2-node packed node term
template<int OUT, int JT2>
__device__ __forceinline__ void nt2_step(float a, float b,
                                         const float* __restrict__ Ws,
                                         int k, int j0,
                                         u64* __restrict__ accA,
                                         u64* __restrict__ accB) {
    if constexpr (JT2 == 4) {
        ulonglong2 w = *reinterpret_cast<const ulonglong2*>(Ws + k * OUT + j0);
        u64 aa = pack2(a, a), bb = pack2(b, b);
        accA[0] = fma2(aa, w.x, accA[0]);
        accA[1] = fma2(aa, w.y, accA[1]);
        accB[0] = fma2(bb, w.x, accB[0]);
        accB[1] = fma2(bb, w.y, accB[1]);
    } else if constexpr (JT2 == 2) {
        u64 w = *reinterpret_cast<const u64*>(Ws + k * OUT + j0);
        accA[0] = fma2(pack2(a, a), w, accA[0]);
        accB[0] = fma2(pack2(b, b), w, accB[0]);
    } else {
        float w = Ws[k * OUT + j0];
        accA[0] = fma2(pack2(a, b), pack2(w, w), accA[0]);   // (nodeA, nodeB)
    }
}

// node term for two nodes (na, nb): accA/accB cover columns j0..j0+JT2-1
template<int IN, int OUT, int JT2>
__device__ __forceinline__ void nodeterm2(const float* __restrict__ S, int soff,
                                          const float* __restrict__ Ws,
                                          u64* __restrict__ accA,
                                          u64* __restrict__ accB,
                                          int na, int nb, int j0) {
    constexpr int NA = (JT2 == 4) ? 2 : 1;
    #pragma unroll
    for (int v = 0; v < NA; v++) { accA[v] = 0ull; accB[v] = 0ull; }
    const float4* sa4 = reinterpret_cast<const float4*>(S + na * STRIDE + soff);
    const float4* sb4 = reinterpret_cast<const float4*>(S + nb * STRIDE + soff);
    constexpr int KB = IN / 4;
    for (int kb = 0; kb < KB; kb++) {
        float4 a4 = sa4[kb], b4 = sb4[kb];
        nt2_step<OUT, JT2>(a4.x, b4.x, Ws, 4 * kb + 0, j0, accA, accB);
        nt2_step<OUT, JT2>(a4.y, b4.y, Ws, 4 * kb + 1, j0, accA, accB);
        nt2_step<OUT, JT2>(a4.z, b4.z, Ws, 4 * kb + 2, j0, accA, accB);
        nt2_step<OUT, JT2>(a4.w, b4.w, Ws, 4 * kb + 3, j0, accA, accB);
    }
    #pragma unroll
    for (int k = KB * 4; k < IN; k++) {
        float a = (S + na * STRIDE + soff)[k];
        float b = (S + nb * STRIDE + soff)[k];
        nt2_step<OUT, JT2>(a, b, Ws, k, j0, accA, accB);
    }
}

// One GCN layer (csl_prev already valid, CTA-synced):
//   basepart(bp slot) -> ARRIVE -> nodeterm(2 nodes) -> WAIT ->
//   per-warp combine (shfl broadcast) -> emit + butterfly colsum -> sync
template<int IN, int OUT, int JT2>
__device__ __forceinline__ void layer_run(
    float* __restrict__ sm, const float* __restrict__ Ssrc, int soff,
    float* __restrict__ D,
    const float* __restrict__ csl_prev, float* __restrict__ csl_next,
    const float* __restrict__ Wb, const float* __restrict__ Wn_,
    const float* __restrict__ bias,
    int slot, int tid, int lane, int na, int nb, int q,
    uint32_t peer, uint32_t smbase)
{
    float* bp = sm + S_BP + slot * 64;

    // base-partial on LOCAL colsum: 4 threads per output column
    if (tid < 4 * OUT) {
        const int j = tid >> 2, p = tid & 3;
        float s = 0.f;
        for (int k = p; k < IN; k += 4) s += csl_prev[k] * Wb[k * OUT + j];
        s += __shfl_xor_sync(0xffffffffu, s, 1);
        s += __shfl_xor_sync(0xffffffffu, s, 2);
        if (p == 0) bp[j] = s;
    }
    CLUSTER_ARRIVE();

    const int j0 = q * JT2;
    u64 accA[(JT2 == 4) ? 2 : 1], accB[(JT2 == 4) ? 2 : 1];
    nodeterm2<IN, OUT, JT2>(Ssrc, soff, Wn_, accA, accB, na, nb, j0);

    CLUSTER_WAIT();   // acquire: local + peer bp visible

    // per-warp combine: lanes 0..JT2-1 compute base[j0+lane], broadcast
    float bmine = 0.f;
    if (lane < JT2) {
        int j = j0 + lane;
        uint32_t la = smbase + (uint32_t)(S_BP + slot * 64 + j) * 4u;
        bmine = bias[j] + bp[j] + ld_peer_f32(la, peer);
    }
    float c0 = __shfl_sync(0xffffffffu, bmine, 0);
    float c1 = (JT2 >= 2) ? __shfl_sync(0xffffffffu, bmine, 1) : 0.f;
    float c2 = (JT2 >= 4) ? __shfl_sync(0xffffffffu, bmine, 2) : 0.f;
    float c3 = (JT2 >= 4) ? __shfl_sync(0xffffffffu, bmine, 3) : 0.f;

    // emit relu(base - acc) for both nodes + fused butterfly colsum
    float* da = D + na * STRIDE + j0;
    float* db = D + nb * STRIDE + j0;
    if constexpr (JT2 == 4) {
        float a0, a1, a2, a3, b0, b1, b2, b3;
        unpack2(accA[0], a0, a1); unpack2(accA[1], a2, a3);
        unpack2(accB[0], b0, b1); unpack2(accB[1], b2, b3);
        float rA0 = fmaxf(c0 - a0, 0.f), rA1 = fmaxf(c1 - a1, 0.f);
        float rA2 = fmaxf(c2 - a2, 0.f), rA3 = fmaxf(c3 - a3, 0.f);
        float rB0 = fmaxf(c0 - b0, 0.f), rB1 = fmaxf(c1 - b1, 0.f);
        float rB2 = fmaxf(c2 - b2, 0.f), rB3 = fmaxf(c3 - b3, 0.f);
        *reinterpret_cast<float4*>(da) = make_float4(rA0, rA1, rA2, rA3);
        *reinterpret_cast<float4*>(db) = make_float4(rB0, rB1, rB2, rB3);
        u64 s01 = warpsum2(pack2(rA0 + rB0, rA1 + rB1));
        u64 s23 = warpsum2(pack2(rA2 + rB2, rA3 + rB3));
        if (lane == 0) {
            float s0, s1, s2, s3;
            unpack2(s01, s0, s1); unpack2(s23, s2, s3);
            *reinterpret_cast<float4*>(csl_next + j0) = make_float4(s0, s1, s2, s3);
        }
    } else if constexpr (JT2 == 2) {
        float a0, a1, b0, b1;
        unpack2(accA[0], a0, a1); unpack2(accB[0], b0, b1);
        float rA0 = fmaxf(c0 - a0, 0.f), rA1 = fmaxf(c1 - a1, 0.f);
        float rB0 = fmaxf(c0 - b0, 0.f), rB1 = fmaxf(c1 - b1, 0.f);
        *reinterpret_cast<float2*>(da) = make_float2(rA0, rA1);
        *reinterpret_cast<float2*>(db) = make_float2(rB0, rB1);
        u64 s01 = warpsum2(pack2(rA0 + rB0, rA1 + rB1));
        if (lane == 0) {
            float s0, s1;
            unpack2(s01, s0, s1);
            *reinterpret_cast<float2*>(csl_next + j0) = make_float2(s0, s1);
        }
    } else {
        float va, vb;
        unpack2(accA[0], va, vb);
        float rA = fmaxf(c0 - va, 0.f), rB = fmaxf(c0 - vb, 0.f);
        da[0] = rA;
        db[0] = rB;
        float s = rA + rB;
        #pragma unroll
        for (int off = 16; off > 0; off >>= 1)
            s += __shfl_xor_sync(0xffffffffu, s, off);
        if (lane == 0) csl_next[j0] = s;
    }
    __syncthreads();   // D + csl_next visible before next layer
}

__global__ __launch_bounds__(THREADS, 1) __cluster_dims__(2, 1, 1)
void gnn_scene_kernel(const float* __restrict__ obj_info,
                      const float* __restrict__ W1, const float* __restrict__ b1,
                      const float* __restrict__ W2, const float* __restrict__ b2,
                      const float* __restrict__ W3, const float* __restrict__ b3,
                      const float* __restrict__ W4, const float* __restrict__ b4,
                      const float* __restrict__ Wn, const float* __restrict__ bn,
                      const float* __restrict__ Wg1, const float* __restrict__ bg1,
                      const float* __restrict__ Wg2, const float* __restrict__ bg2,
                      float* __restrict__ out) {
    extern __shared__ float sm[];
    const int tid  = threadIdx.x;
    const int lane = tid & 31;
    const int b    = blockIdx.x >> 1;
    const uint32_t rank = blockIdx.x & 1;
    const uint32_t peer = rank ^ 1u;
    const int na = tid & 31;            // node a (0..31)
    const int nb = na + 32;             // node b (32..63)
    const int q  = tid >> 5;            // column group 0..15
    const uint32_t smbase = smem_u32(sm);

    // ---- load + prescale weights (float4) ----
    {
        const float4* w14 = reinterpret_cast<const float4*>(W1);
        for (int i = tid; i < 80; i += THREADS) {
            float4 w = w14[i];
            reinterpret_cast<float4*>(sm + S_W1s)[i] =
                make_float4(w.x * INV127, w.y * INV127, w.z * INV127, w.w * INV127);
            const float s = 128.0f * INV127;
            reinterpret_cast<float4*>(sm + S_W1s128)[i] =
                make_float4(w.x * s, w.y * s, w.z * s, w.w * s);
        }
    }
    #define CPYS4(dst, src, cnt4) { \
        const float4* s4_ = reinterpret_cast<const float4*>(src); \
        for (int i = tid; i < (cnt4); i += THREADS) { \
            float4 w = s4_[i]; \
            reinterpret_cast<float4*>(sm + (dst))[i] = \
                make_float4(w.x * INV127, w.y * INV127, w.z * INV127, w.w * INV127); \
        } }
    #define CPY(dst, src, cnt) \
        for (int i = tid; i < (cnt); i += THREADS) sm[(dst) + i] = src[i];
    CPYS4(S_W2s, W2, 1200);  CPY(S_B2, b2, 64);
    CPYS4(S_W3s, W3, 512);   CPY(S_B3, b3, 32);
    CPYS4(S_W4s, W4, 128);   CPY(S_B4, b4, 16);
    for (int i = tid; i < 32; i += THREADS) sm[S_WNs + i] = Wn[i] * INV127;
    CPY(S_BN, bn, 2);
    CPY(S_B1, b1, 64);
    CPY(S_WG1, Wg1, 16*8);   CPY(S_BG1, bg1, 8);
    CPY(S_WG2, Wg2, 8);      CPY(S_BG2, bg2, 1);
    #undef CPYS4
    #undef CPY

    // ---- load this CTA's 64 rows of info[b] into A cols 64..74 ----
    {
        const float* src = obj_info + ((size_t)b * NODES + rank * LOCALN) * 11;
        for (int i = tid; i < LOCALN * 11; i += THREADS) {
            int r = i / 11, c = i % 11;
            sm[S_A + r * STRIDE + 64 + c] = src[i];
        }
    }
    __syncthreads();

    float* A  = sm + S_A;
    float* Bb = sm + S_BUF;

    // ---- info colsum (11 cols x 64 rows) -> cs2[64..74] ----
    if (tid < 11 * 16) {
        int c = tid % 11, p = tid / 11;
        float s = 0.f;
        #pragma unroll
        for (int r = 0; r < 4; r++) s += A[(p * 4 + r) * STRIDE + 64 + c];
        sm[S_PART + p * 11 + c] = s;
    }
    __syncthreads();
    if (tid < 11) {
        float s = 0.f;
        #pragma unroll
        for (int p = 0; p < 16; p++) s += sm[S_PART + p * 11 + tid];
        sm[S_CS2 + 64 + tid] = s;
    }
    __syncthreads();

    // L1 (edge): info (A cols 64..68) -> h1 (A cols 0..63); colsum -> cs2[0..63]
    layer_run<5, 64, 4>(sm, A, 64, A, sm + S_CS2 + 64, sm + S_CS2,
                        sm + S_W1s, sm + S_W1s128, sm + S_B1,
                        0, tid, lane, na, nb, q, peer, smbase);

    // L2: h75 (A cols 0..74; cs2[0..74]) -> h2 (Bb); colsum -> cs3
    layer_run<75, 64, 4>(sm, A, 0, Bb, sm + S_CS2, sm + S_CS3,
                         sm + S_W2s, sm + S_W2s, sm + S_B2,
                         1, tid, lane, na, nb, q, peer, smbase);

    // L3: h2 -> h3 (A cols 0..31); colsum -> cs4
    layer_run<64, 32, 2>(sm, Bb, 0, A, sm + S_CS3, sm + S_CS4,
                         sm + S_W3s, sm + S_W3s, sm + S_B3,
                         0, tid, lane, na, nb, q, peer, smbase);

    // L4: h3 -> h4 (Bb cols 0..15); colsum -> cs5
    layer_run<32, 16, 1>(sm, A, 0, Bb, sm + S_CS4, sm + S_CS5,
                         sm + S_W4s, sm + S_W4s, sm + S_B4,
                         1, tid, lane, na, nb, q, peer, smbase);

    // ---- heads on h4 (Bb cols 0..15; local colsum = cs5) ----
    {
        float* csl = sm + S_CS5;
        float* bp  = sm + S_BP;       // slot 0 (safe: L4 cluster barrier passed)
        if (tid < 8) {
            int j = tid >> 2, p = tid & 3;
            float s = 0.f;
            for (int k = p; k < 16; k += 4) s += csl[k] * sm[S_WNs + k * 2 + j];
            s += __shfl_xor_sync(0xffu, s, 1);
            s += __shfl_xor_sync(0xffu, s, 2);
            if (p == 0) bp[j] = s;
        }
        CLUSTER_ARRIVE();
        float accnA = 0.f, accnB = 0.f;
        if (q < 2) {   // warps 0,1: column j=q for both nodes
            const float* sa = Bb + na * STRIDE;
            const float* sb = Bb + nb * STRIDE;
            #pragma unroll
            for (int k = 0; k < 16; k++) {
                float w = sm[S_WNs + k * 2 + q];
                accnA += sa[k] * w;
                accnB += sb[k] * w;
            }
        }
        CLUSTER_WAIT();
        if (q < 2) {
            float baseq = 0.f;
            if (lane == 0) {
                uint32_t la = smbase + (uint32_t)(S_BP + q) * 4u;
                baseq = sm[S_BN + q] + bp[q] + ld_peer_f32(la, peer);
            }
            baseq = __shfl_sync(0xffffffffu, baseq, 0);
            size_t g0 = (size_t)b * NODES + rank * LOCALN;
            out[64 + (g0 + na) * 2 + q] = baseq - accnA;
            out[64 + (g0 + nb) * 2 + q] = baseq - accnB;
        }

        // scene head: rank 0, thread 0 pulls peer cs5 itself
        if (rank == 0 && tid == 0) {
            float scene[16];
            #pragma unroll
            for (int k = 0; k < 16; k++) {
                uint32_t la = smbase + (uint32_t)(S_CS5 + k) * 4u;
                scene[k] = (csl[k] + ld_peer_f32(la, peer)) * (1.0f / NODES);
            }
            float z = sm[S_BG2];
            #pragma unroll
            for (int o = 0; o < 8; o++) {
                float g = sm[S_BG1 + o];
                #pragma unroll
                for (int k = 0; k < 16; k++) g += scene[k] * sm[S_WG1 + k * 8 + o];
                g = fmaxf(g, 0.f);
                z += g * sm[S_WG2 + o];
            }
            out[b] = 1.0f / (1.0f + expf(-z));
        }
    }

    // no CTA may exit while the peer might still read its smem via DSMEM
    CLUSTER_ARRIVE();
    CLUSTER_WAIT();
}

extern "C" void kernel_launch(void* const* d_in, const int* in_sizes, int n_in,
                              void* d_out, int out_size) {
    const float* obj = (const float*)d_in[0];
    const float* W1  = (const float*)d_in[1];
    const float* b1  = (const float*)d_in[2];
    const float* W2  = (const float*)d_in[3];
    const float* b2  = (const float*)d_in[4];
    const float* W3  = (const float*)d_in[5];
    const float* b3  = (const float*)d_in[6];
    const float* W4  = (const float*)d_in[7];
    const float* b4  = (const float*)d_in[8];
    const float* Wn  = (const float*)d_in[9];
    const float* bn  = (const float*)d_in[10];
    const float* Wg1 = (const float*)d_in[11];
    const float* bg1 = (const float*)d_in[12];
    const float* Wg2 = (const float*)d_in[13];
    const float* bg2 = (const float*)d_in[14];
    // d_in[15]=src, d_in[16]=dst: complete graph, exploited analytically.

    cudaFuncSetAttribute(gnn_scene_kernel,
                         cudaFuncAttributeMaxDynamicSharedMemorySize, SMEM_BYTES);
    gnn_scene_kernel<<<SCENES * 2, THREADS, SMEM_BYTES>>>(
        obj, W1, b1, W2, b2, W3, b3, W4, b4, Wn, bn, Wg1, bg1, Wg2, bg2,
        (float*)d_out);
}